// round 1
// baseline (speedup 1.0000x reference)
#include <cuda_runtime.h>

#define H 128

// Scratch for per-node layer-1 partials:
// [gd: gene@W1a | gd: disease@W1b+b1 | gg: gene@W1a | gg: gene@W1b+b1]
// Worst case (3*100000 + 20000) * 128 floats = 40.96M floats; pad a little.
__device__ float g_P[42000000];

// ---------------------------------------------------------------------------
// Kernel 1: four dense GEMMs  C[M,128] = A[M,128] @ W[128,128] (+ bias)
// blockIdx.y selects which GEMM. 64-row tiles, 256 threads, 8x4 register tile.
// ---------------------------------------------------------------------------
__global__ void __launch_bounds__(256)
gemm_partial_kernel(const float* __restrict__ zg, const float* __restrict__ zd,
                    const float* __restrict__ w1_gd, const float* __restrict__ b1_gd,
                    const float* __restrict__ w1_gg, const float* __restrict__ b1_gg,
                    int n_gene, int n_dis)
{
    const int g = blockIdx.y;
    const float* A;
    const float* W;
    const float* bias = nullptr;
    int M;
    size_t outOff;
    const size_t ng = (size_t)n_gene * H;
    const size_t nd = (size_t)n_dis * H;

    if (g == 0)      { A = zg; W = w1_gd;           M = n_gene; outOff = 0;            }
    else if (g == 1) { A = zd; W = w1_gd + 128 * H; M = n_dis;  outOff = ng;           bias = b1_gd; }
    else if (g == 2) { A = zg; W = w1_gg;           M = n_gene; outOff = ng + nd;      }
    else             { A = zg; W = w1_gg + 128 * H; M = n_gene; outOff = ng + nd + ng; bias = b1_gg; }

    const int m0 = blockIdx.x * 64;
    if (m0 >= M) return;

    __shared__ float As[64][32];   // A chunk: 64 rows x 32 k
    __shared__ float Ws[32][128];  // W chunk: 32 k x 128 cols

    const int tid = threadIdx.x;
    const int tx  = tid & 31;   // col group: cols 4*tx .. 4*tx+3
    const int ty  = tid >> 5;   // row group: rows ty*8 .. ty*8+7 (warp-uniform)

    float acc[8][4];
    #pragma unroll
    for (int r = 0; r < 8; r++)
        #pragma unroll
        for (int c = 0; c < 4; c++)
            acc[r][c] = 0.0f;

    for (int kk = 0; kk < H; kk += 32) {
        __syncthreads();  // protect previous iteration's smem reads

        // Load A chunk: 64x32 = 512 float4, 2 per thread
        #pragma unroll
        for (int i = 0; i < 2; i++) {
            int idx = tid + 256 * i;          // 0..511
            int row = idx >> 3;               // 0..63
            int c4  = idx & 7;                // 0..7  (8 float4 per row)
            float4 v = make_float4(0.f, 0.f, 0.f, 0.f);
            if (m0 + row < M)
                v = *(const float4*)&A[(size_t)(m0 + row) * H + kk + c4 * 4];
            *(float4*)&As[row][c4 * 4] = v;
        }
        // Load W chunk: 32x128 = 1024 float4, 4 per thread
        #pragma unroll
        for (int i = 0; i < 4; i++) {
            int idx = tid + 256 * i;          // 0..1023
            int row = idx >> 5;               // 0..31
            int c4  = idx & 31;               // 0..31
            *(float4*)&Ws[row][c4 * 4] =
                *(const float4*)&W[(size_t)(kk + row) * H + c4 * 4];
        }
        __syncthreads();

        #pragma unroll
        for (int k = 0; k < 32; k++) {
            float4 w = *(float4*)&Ws[k][tx * 4];
            #pragma unroll
            for (int r = 0; r < 8; r++) {
                float a = As[ty * 8 + r][k];  // warp-broadcast
                acc[r][0] = fmaf(a, w.x, acc[r][0]);
                acc[r][1] = fmaf(a, w.y, acc[r][1]);
                acc[r][2] = fmaf(a, w.z, acc[r][2]);
                acc[r][3] = fmaf(a, w.w, acc[r][3]);
            }
        }
    }

    float4 bv = make_float4(0.f, 0.f, 0.f, 0.f);
    if (bias) bv = *(const float4*)&bias[tx * 4];

    #pragma unroll
    for (int r = 0; r < 8; r++) {
        int m = m0 + ty * 8 + r;
        if (m < M) {
            float4 o;
            o.x = acc[r][0] + bv.x;
            o.y = acc[r][1] + bv.y;
            o.z = acc[r][2] + bv.z;
            o.w = acc[r][3] + bv.w;
            *(float4*)&g_P[outOff + (size_t)m * H + tx * 4] = o;
        }
    }
}

// ---------------------------------------------------------------------------
// Kernel 2: per-edge combine.  One warp per edge (grid-stride):
//   h = relu(Psrc[src] + Pdst[dst]);  out = h . w2 + b2
// blockIdx.y = relation (0: gene->disease, 1: gene->gene)
// ---------------------------------------------------------------------------
__global__ void __launch_bounds__(256)
edge_decode_kernel(const int* __restrict__ edges_gd, const int* __restrict__ edges_gg,
                   const float* __restrict__ w2_gd, const float* __restrict__ b2_gd,
                   const float* __restrict__ w2_gg, const float* __restrict__ b2_gg,
                   float* __restrict__ out, int E, int n_gene, int n_dis)
{
    const int rel = blockIdx.y;
    const size_t ng = (size_t)n_gene * H;
    const size_t nd = (size_t)n_dis * H;

    const int*   edges = rel ? edges_gg : edges_gd;
    const float* Psrc  = rel ? (g_P + ng + nd)      : g_P;
    const float* Pdst  = rel ? (g_P + ng + nd + ng) : (g_P + ng);
    const float* w2    = rel ? w2_gg : w2_gd;
    const float  b2    = (rel ? b2_gg : b2_gd)[0];
    float* o = out + (size_t)rel * E;

    const int lane   = threadIdx.x & 31;
    const int warp   = (blockIdx.x * blockDim.x + threadIdx.x) >> 5;
    const int nwarps = (gridDim.x * blockDim.x) >> 5;

    const float4 w = *(const float4*)&w2[lane * 4];

    for (int e = warp; e < E; e += nwarps) {
        const int s = edges[e];
        const int d = edges[E + e];
        const float4 a = *(const float4*)&Psrc[(size_t)s * H + lane * 4];
        const float4 b = *(const float4*)&Pdst[(size_t)d * H + lane * 4];

        float sum;
        sum  = fmaxf(a.x + b.x, 0.f) * w.x;
        sum += fmaxf(a.y + b.y, 0.f) * w.y;
        sum += fmaxf(a.z + b.z, 0.f) * w.z;
        sum += fmaxf(a.w + b.w, 0.f) * w.w;

        #pragma unroll
        for (int off = 16; off; off >>= 1)
            sum += __shfl_xor_sync(0xFFFFFFFFu, sum, off);

        if (lane == 0) o[e] = sum + b2;
    }
}

// ---------------------------------------------------------------------------
extern "C" void kernel_launch(void* const* d_in, const int* in_sizes, int n_in,
                              void* d_out, int out_size)
{
    const float* z_gene = (const float*)d_in[0];
    const float* z_dis  = (const float*)d_in[1];
    const int*   e_gd   = (const int*)  d_in[2];
    const int*   e_gg   = (const int*)  d_in[3];
    const float* w1_gd  = (const float*)d_in[4];
    const float* b1_gd  = (const float*)d_in[5];
    const float* w2_gd  = (const float*)d_in[6];
    const float* b2_gd  = (const float*)d_in[7];
    const float* w1_gg  = (const float*)d_in[8];
    const float* b1_gg  = (const float*)d_in[9];
    const float* w2_gg  = (const float*)d_in[10];
    const float* b2_gg  = (const float*)d_in[11];

    const int n_gene = in_sizes[0] / H;
    const int n_dis  = in_sizes[1] / H;
    const int E      = in_sizes[2] / 2;

    int mmax = n_gene > n_dis ? n_gene : n_dis;
    dim3 ggrid((mmax + 63) / 64, 4);
    gemm_partial_kernel<<<ggrid, 256>>>(z_gene, z_dis, w1_gd, b1_gd, w1_gg, b1_gg,
                                        n_gene, n_dis);

    dim3 egrid(1184, 2);
    edge_decode_kernel<<<egrid, 256>>>(e_gd, e_gg, w2_gd, b2_gd, w2_gg, b2_gg,
                                       (float*)d_out, E, n_gene, n_dis);
}

// round 3
// speedup vs baseline: 1.0518x; 1.0518x over previous
#include <cuda_runtime.h>
#include <cuda_bf16.h>
#include <cstdint>

#define H 128

// ---------------------------------------------------------------------------
// Global scratch (no allocations allowed)
// ---------------------------------------------------------------------------
// Per-node layer-1 partials: [gd_gene | gd_dis | gg_src | gg_dst]
__device__ float g_P[42000000];
// bf16 split weights, transposed: [part][hi/lo][n][k]
// part: 0 = w1_gd[:128], 1 = w1_gg[:128], 2 = w1_gg[128:], 3 = w1_gd[128:]
__device__ __nv_bfloat16 g_Wb[4 * 2 * H * H];

// ---------------------------------------------------------------------------
// helpers
// ---------------------------------------------------------------------------
__device__ __forceinline__ uint32_t smem_u32(const void* p){
    uint32_t a;
    asm("{ .reg .u64 t; cvta.to.shared.u64 t, %1; cvt.u32.u64 %0, t; }" : "=r"(a) : "l"(p));
    return a;
}
__device__ __forceinline__ void ldsm4(uint32_t* r, uint32_t addr){
    asm volatile("ldmatrix.sync.aligned.m8n8.x4.shared.b16 {%0,%1,%2,%3}, [%4];"
        : "=r"(r[0]), "=r"(r[1]), "=r"(r[2]), "=r"(r[3]) : "r"(addr));
}
__device__ __forceinline__ void mma_bf16(float* d, const uint32_t* a,
                                         uint32_t b0, uint32_t b1){
    asm volatile("mma.sync.aligned.m16n8k16.row.col.f32.bf16.bf16.f32 "
        "{%0,%1,%2,%3}, {%4,%5,%6,%7}, {%8,%9}, {%0,%1,%2,%3};"
        : "+f"(d[0]), "+f"(d[1]), "+f"(d[2]), "+f"(d[3])
        : "r"(a[0]), "r"(a[1]), "r"(a[2]), "r"(a[3]), "r"(b0), "r"(b1));
}
__device__ __forceinline__ uint32_t pack2bf(float a, float b){
    __nv_bfloat162 t = __floats2bfloat162_rn(a, b);   // .x=a (low), .y=b (high)
    return *(uint32_t*)&t;
}

// XOR-swizzled byte offset inside a [128 rows x 128 bf16] tile (256B rows).
// 16B chunk kc (0..15) of row r lives at slot (kc ^ (r&7)).
__device__ __forceinline__ uint32_t toff(int r, int kc){
    return (uint32_t)r * 256u + (uint32_t)((kc ^ (r & 7)) << 4);
}

// smem map: A-hi | A-lo | B-hi | B-lo, 32KB each
#define SM_AH 0
#define SM_AL 32768
#define SM_BH 65536
#define SM_BL 98304
#define SM_TOTAL 131072

// ---------------------------------------------------------------------------
// Kernel 0: split+transpose the four 128x128 W blocks -> bf16 hi/lo, [n][k]
// ---------------------------------------------------------------------------
__global__ void prep_w_kernel(const float* __restrict__ w1_gd,
                              const float* __restrict__ w1_gg)
{
    int idx = blockIdx.x * blockDim.x + threadIdx.x;  // 4*128*128
    if (idx >= 4 * H * H) return;
    int part = idx >> 14;
    int n = (idx >> 7) & 127;
    int k = idx & 127;
    const float* Wsrc = (part == 0) ? w1_gd
                      : (part == 1) ? w1_gg
                      : (part == 2) ? (w1_gg + H * H)
                                    : (w1_gd + H * H);
    float x = Wsrc[k * H + n];
    __nv_bfloat16 hi = __float2bfloat16_rn(x);
    __nv_bfloat16 lo = __float2bfloat16_rn(x - __bfloat162float(hi));
    g_Wb[((size_t)(part * 2 + 0) * H + n) * H + k] = hi;
    g_Wb[((size_t)(part * 2 + 1) * H + n) * H + k] = lo;
}

// ---------------------------------------------------------------------------
// Kernel 1: tensor-core GEMM via mma.sync bf16 split-2.
// One 128x128 output tile per CTA; 8 warps in 4x2; 3 passes (hi*hi, lo*hi, hi*lo).
// ---------------------------------------------------------------------------
__global__ void __launch_bounds__(256, 1)
gemm_tc_kernel(const float* __restrict__ zg, const float* __restrict__ zd,
               const float* __restrict__ b1_gd, const float* __restrict__ b1_gg,
               int n_gene, int n_dis)
{
    extern __shared__ char smem[];
    const uint32_t sb = smem_u32(smem);
    const int tid = threadIdx.x;

    const int tg = (n_gene + 127) >> 7;
    const size_t ng = (size_t)n_gene * H, nd = (size_t)n_dis * H;

    int b = blockIdx.x;
    const float* A; const float* bias = nullptr; int M; size_t outOff; int part; int tile;
    if (b < tg)          { part = 0; tile = b;          A = zg; M = n_gene; outOff = 0; }
    else if (b < 2 * tg) { part = 1; tile = b - tg;     A = zg; M = n_gene; outOff = ng + nd; }
    else if (b < 3 * tg) { part = 2; tile = b - 2 * tg; A = zg; M = n_gene; outOff = ng + nd + ng; bias = b1_gg; }
    else                 { part = 3; tile = b - 3 * tg; A = zd; M = n_dis;  outOff = ng; bias = b1_gd; }
    const int m0 = tile << 7;

    // ---- stage A (fp32 -> bf16 hi/lo) ----
    #pragma unroll
    for (int i = 0; i < 8; i++) {
        int u = tid + 256 * i;          // 0..2047 : (row, 8-float chunk)
        int r = u >> 4, c8 = u & 15;
        float4 v0 = make_float4(0.f,0.f,0.f,0.f), v1 = v0;
        if (m0 + r < M) {
            const float* ap = &A[(size_t)(m0 + r) * H + c8 * 8];
            v0 = *(const float4*)ap;
            v1 = *(const float4*)(ap + 4);
        }
        float f[8] = {v0.x,v0.y,v0.z,v0.w,v1.x,v1.y,v1.z,v1.w};
        uint32_t hi[4], lo[4];
        #pragma unroll
        for (int j = 0; j < 4; j++) {
            float a0 = f[2*j], a1 = f[2*j+1];
            float h0 = __bfloat162float(__float2bfloat16_rn(a0));
            float h1 = __bfloat162float(__float2bfloat16_rn(a1));
            hi[j] = pack2bf(a0, a1);
            lo[j] = pack2bf(a0 - h0, a1 - h1);
        }
        uint32_t o = toff(r, c8);
        *(uint4*)(smem + SM_AH + o) = make_uint4(hi[0],hi[1],hi[2],hi[3]);
        *(uint4*)(smem + SM_AL + o) = make_uint4(lo[0],lo[1],lo[2],lo[3]);
    }
    // ---- stage B (already bf16 hi/lo in gmem, [n][k]) ----
    {
        const uint4* bh = (const uint4*)(g_Wb + (size_t)(part * 2 + 0) * H * H);
        const uint4* bl = (const uint4*)(g_Wb + (size_t)(part * 2 + 1) * H * H);
        #pragma unroll
        for (int i = 0; i < 8; i++) {
            int u = tid + 256 * i;      // chunk id: row = u>>4, kc = u&15
            int r = u >> 4, kc = u & 15;
            uint32_t o = toff(r, kc);
            *(uint4*)(smem + SM_BH + o) = bh[u];
            *(uint4*)(smem + SM_BL + o) = bl[u];
        }
    }
    __syncthreads();

    // ---- compute ----
    const int lane = tid & 31, w = tid >> 5;
    const int wr = w >> 1, wc = w & 1;        // warp tile: rows wr*32, cols wc*64

    float acc[2][8][4];
    #pragma unroll
    for (int mt = 0; mt < 2; mt++)
        #pragma unroll
        for (int nt = 0; nt < 8; nt++)
            #pragma unroll
            for (int q = 0; q < 4; q++) acc[mt][nt][q] = 0.f;

    const int arow = wr * 32 + (lane & 15);          // + mt*16
    const int akh  = lane >> 4;                      // k-half within k16
    const int brow = wc * 64 + (lane & 7) + ((lane >> 4) << 3);  // + np*16
    const int bkh  = (lane >> 3) & 1;

    #pragma unroll
    for (int pass = 0; pass < 3; pass++) {
        const uint32_t aBase = sb + (pass == 1 ? SM_AL : SM_AH);
        const uint32_t bBase = sb + (pass == 2 ? SM_BL : SM_BH);
        #pragma unroll
        for (int s = 0; s < 8; s++) {
            uint32_t afr[2][4];
            #pragma unroll
            for (int mt = 0; mt < 2; mt++)
                ldsm4(afr[mt], aBase + toff(arow + mt * 16, 2 * s + akh));
            uint32_t bfr[4][4];
            #pragma unroll
            for (int np = 0; np < 4; np++)
                ldsm4(bfr[np], bBase + toff(brow + np * 16, 2 * s + bkh));
            #pragma unroll
            for (int mt = 0; mt < 2; mt++)
                #pragma unroll
                for (int nt = 0; nt < 8; nt++)
                    mma_bf16(acc[mt][nt], afr[mt],
                             bfr[nt >> 1][(nt & 1) * 2], bfr[nt >> 1][(nt & 1) * 2 + 1]);
        }
    }

    // ---- writeout ----
    const int rbase = m0 + wr * 32 + (lane >> 2);
    const int cbase = wc * 64 + (lane & 3) * 2;
    #pragma unroll
    for (int mt = 0; mt < 2; mt++) {
        #pragma unroll
        for (int nt = 0; nt < 8; nt++) {
            int n = cbase + nt * 8;
            float bx = 0.f, by = 0.f;
            if (bias) { float2 bv = *(const float2*)&bias[n]; bx = bv.x; by = bv.y; }
            int r0 = rbase + mt * 16;
            if (r0 < M + m0 - m0 && (r0 < M)) { /* r0 relative check below */ }
            int rr0 = rbase + mt * 16;
            int rr1 = rr0 + 8;
            if (rr0 < M) {
                float2 o0 = make_float2(acc[mt][nt][0] + bx, acc[mt][nt][1] + by);
                *(float2*)&g_P[outOff + (size_t)rr0 * H + n] = o0;
            }
            if (rr1 < M) {
                float2 o1 = make_float2(acc[mt][nt][2] + bx, acc[mt][nt][3] + by);
                *(float2*)&g_P[outOff + (size_t)rr1 * H + n] = o1;
            }
        }
    }
}

// ---------------------------------------------------------------------------
// Kernel 2: per-edge combine. One warp per edge (grid-stride).
// ---------------------------------------------------------------------------
__global__ void __launch_bounds__(256)
edge_decode_kernel(const int* __restrict__ edges_gd, const int* __restrict__ edges_gg,
                   const float* __restrict__ w2_gd, const float* __restrict__ b2_gd,
                   const float* __restrict__ w2_gg, const float* __restrict__ b2_gg,
                   float* __restrict__ out, int E, int n_gene, int n_dis)
{
    const int rel = blockIdx.y;
    const size_t ng = (size_t)n_gene * H;
    const size_t nd = (size_t)n_dis * H;

    const int*   edges = rel ? edges_gg : edges_gd;
    const float* Psrc  = rel ? (g_P + ng + nd)      : g_P;
    const float* Pdst  = rel ? (g_P + ng + nd + ng) : (g_P + ng);
    const float* w2    = rel ? w2_gg : w2_gd;
    const float  b2    = (rel ? b2_gg : b2_gd)[0];
    float* o = out + (size_t)rel * E;

    const int lane   = threadIdx.x & 31;
    const int warp   = (blockIdx.x * blockDim.x + threadIdx.x) >> 5;
    const int nwarps = (gridDim.x * blockDim.x) >> 5;

    const float4 w = *(const float4*)&w2[lane * 4];

    for (int e = warp; e < E; e += nwarps) {
        const int s = edges[e];
        const int d = edges[E + e];
        const float4 a = *(const float4*)&Psrc[(size_t)s * H + lane * 4];
        const float4 b = *(const float4*)&Pdst[(size_t)d * H + lane * 4];

        float sum;
        sum  = fmaxf(a.x + b.x, 0.f) * w.x;
        sum += fmaxf(a.y + b.y, 0.f) * w.y;
        sum += fmaxf(a.z + b.z, 0.f) * w.z;
        sum += fmaxf(a.w + b.w, 0.f) * w.w;

        #pragma unroll
        for (int off = 16; off; off >>= 1)
            sum += __shfl_xor_sync(0xFFFFFFFFu, sum, off);

        if (lane == 0) o[e] = sum + b2;
    }
}

// ---------------------------------------------------------------------------
extern "C" void kernel_launch(void* const* d_in, const int* in_sizes, int n_in,
                              void* d_out, int out_size)
{
    const float* z_gene = (const float*)d_in[0];
    const float* z_dis  = (const float*)d_in[1];
    const int*   e_gd   = (const int*)  d_in[2];
    const int*   e_gg   = (const int*)  d_in[3];
    const float* w1_gd  = (const float*)d_in[4];
    const float* b1_gd  = (const float*)d_in[5];
    const float* w2_gd  = (const float*)d_in[6];
    const float* b2_gd  = (const float*)d_in[7];
    const float* w1_gg  = (const float*)d_in[8];
    const float* b1_gg  = (const float*)d_in[9];
    const float* w2_gg  = (const float*)d_in[10];
    const float* b2_gg  = (const float*)d_in[11];

    const int n_gene = in_sizes[0] / H;
    const int n_dis  = in_sizes[1] / H;
    const int E      = in_sizes[2] / 2;

    static bool attr_done = false;
    if (!attr_done) {
        cudaFuncSetAttribute(gemm_tc_kernel,
                             cudaFuncAttributeMaxDynamicSharedMemorySize, SM_TOTAL);
        attr_done = true;
    }

    prep_w_kernel<<<(4 * H * H + 255) / 256, 256>>>(w1_gd, w1_gg);

    const int tg = (n_gene + 127) >> 7;
    const int td = (n_dis + 127) >> 7;
    gemm_tc_kernel<<<3 * tg + td, 256, SM_TOTAL>>>(z_gene, z_dis, b1_gd, b1_gg,
                                                   n_gene, n_dis);

    dim3 egrid(1184, 2);
    edge_decode_kernel<<<egrid, 256>>>(e_gd, e_gg, w2_gd, b2_gd, w2_gg, b2_gg,
                                       (float*)d_out, E, n_gene, n_dis);
}

// round 4
// speedup vs baseline: 1.9834x; 1.8856x over previous
#include <cuda_runtime.h>
#include <cuda_fp16.h>
#include <cstdint>

#define H 128

// ---------------------------------------------------------------------------
// Global scratch (no allocations allowed)
// ---------------------------------------------------------------------------
// Per-node layer-1 partials in fp16: [gd_gene | gd_dis | gg_src | gg_dst]
__device__ __half g_Ph[42000000];
// fp16 split weights, transposed: [part][hi/lo][n][k]
// part: 0 = w1_gd[:128], 1 = w1_gg[:128], 2 = w1_gg[128:], 3 = w1_gd[128:]
__device__ __half g_Wh[4 * 2 * H * H];

// ---------------------------------------------------------------------------
// helpers
// ---------------------------------------------------------------------------
__device__ __forceinline__ uint32_t smem_u32(const void* p){
    uint32_t a;
    asm("{ .reg .u64 t; cvta.to.shared.u64 t, %1; cvt.u32.u64 %0, t; }" : "=r"(a) : "l"(p));
    return a;
}
__device__ __forceinline__ void ldsm4(uint32_t* r, uint32_t addr){
    asm volatile("ldmatrix.sync.aligned.m8n8.x4.shared.b16 {%0,%1,%2,%3}, [%4];"
        : "=r"(r[0]), "=r"(r[1]), "=r"(r[2]), "=r"(r[3]) : "r"(addr));
}
__device__ __forceinline__ void mma_f16(float* d, const uint32_t* a,
                                        uint32_t b0, uint32_t b1){
    asm volatile("mma.sync.aligned.m16n8k16.row.col.f32.f16.f16.f32 "
        "{%0,%1,%2,%3}, {%4,%5,%6,%7}, {%8,%9}, {%0,%1,%2,%3};"
        : "+f"(d[0]), "+f"(d[1]), "+f"(d[2]), "+f"(d[3])
        : "r"(a[0]), "r"(a[1]), "r"(a[2]), "r"(a[3]), "r"(b0), "r"(b1));
}

// XOR-swizzled byte offset inside a [128 rows x 128 fp16] tile (256B rows).
// 16B chunk kc (0..15) of row r lives at slot (kc ^ (r&7)).
__device__ __forceinline__ uint32_t toff(int r, int kc){
    return (uint32_t)r * 256u + (uint32_t)((kc ^ (r & 7)) << 4);
}

// smem map: A-hi 32KB | B-hi 32KB | B-lo 32KB
#define SM_A  0
#define SM_BH 32768
#define SM_BL 65536
#define SM_TOTAL 98304

// ---------------------------------------------------------------------------
// Kernel 0: split+transpose the four 128x128 W blocks -> fp16 hi/lo, [n][k]
// ---------------------------------------------------------------------------
__global__ void prep_w_kernel(const float* __restrict__ w1_gd,
                              const float* __restrict__ w1_gg)
{
    int idx = blockIdx.x * blockDim.x + threadIdx.x;  // 4*128*128
    if (idx >= 4 * H * H) return;
    int part = idx >> 14;
    int n = (idx >> 7) & 127;
    int k = idx & 127;
    const float* Wsrc = (part == 0) ? w1_gd
                      : (part == 1) ? w1_gg
                      : (part == 2) ? (w1_gg + H * H)
                                    : (w1_gd + H * H);
    float x = Wsrc[k * H + n];
    __half hi = __float2half_rn(x);
    __half lo = __float2half_rn(x - __half2float(hi));
    g_Wh[((size_t)(part * 2 + 0) * H + n) * H + k] = hi;
    g_Wh[((size_t)(part * 2 + 1) * H + n) * H + k] = lo;
}

// ---------------------------------------------------------------------------
// Kernel 1: tensor-core GEMM via mma.sync fp16.
// C = A_hi @ (B_hi + B_lo)^T  (fp32 accum). One 128x128 tile / CTA, occ=2.
// ---------------------------------------------------------------------------
__global__ void __launch_bounds__(256, 2)
gemm_tc_kernel(const float* __restrict__ zg, const float* __restrict__ zd,
               const float* __restrict__ b1_gd, const float* __restrict__ b1_gg,
               int n_gene, int n_dis)
{
    extern __shared__ char smem[];
    const uint32_t sb = smem_u32(smem);
    const int tid = threadIdx.x;

    const int tg = (n_gene + 127) >> 7;
    const size_t ng = (size_t)n_gene * H, nd = (size_t)n_dis * H;

    int b = blockIdx.x;
    const float* A; const float* bias = nullptr; int M; size_t outOff; int part; int tile;
    if (b < tg)          { part = 0; tile = b;          A = zg; M = n_gene; outOff = 0; }
    else if (b < 2 * tg) { part = 1; tile = b - tg;     A = zg; M = n_gene; outOff = ng + nd; }
    else if (b < 3 * tg) { part = 2; tile = b - 2 * tg; A = zg; M = n_gene; outOff = ng + nd + ng; bias = b1_gg; }
    else                 { part = 3; tile = b - 3 * tg; A = zd; M = n_dis;  outOff = ng; bias = b1_gd; }
    const int m0 = tile << 7;

    // ---- stage A (fp32 -> fp16 hi only) ----
    #pragma unroll
    for (int i = 0; i < 8; i++) {
        int u = tid + 256 * i;          // (row, 16B chunk) of the tile
        int r = u >> 4, c8 = u & 15;
        float4 v0 = make_float4(0.f,0.f,0.f,0.f), v1 = v0;
        if (m0 + r < M) {
            const float* ap = &A[(size_t)(m0 + r) * H + c8 * 8];
            v0 = *(const float4*)ap;
            v1 = *(const float4*)(ap + 4);
        }
        __half2 h0 = __floats2half2_rn(v0.x, v0.y);
        __half2 h1 = __floats2half2_rn(v0.z, v0.w);
        __half2 h2 = __floats2half2_rn(v1.x, v1.y);
        __half2 h3 = __floats2half2_rn(v1.z, v1.w);
        uint4 pk = make_uint4(*(uint32_t*)&h0, *(uint32_t*)&h1,
                              *(uint32_t*)&h2, *(uint32_t*)&h3);
        *(uint4*)(smem + SM_A + toff(r, c8)) = pk;
    }
    // ---- stage B hi/lo (fp16 in gmem, [n][k]) ----
    {
        const uint4* bh = (const uint4*)(g_Wh + (size_t)(part * 2 + 0) * H * H);
        const uint4* bl = (const uint4*)(g_Wh + (size_t)(part * 2 + 1) * H * H);
        #pragma unroll
        for (int i = 0; i < 8; i++) {
            int u = tid + 256 * i;
            int r = u >> 4, kc = u & 15;
            uint32_t o = toff(r, kc);
            *(uint4*)(smem + SM_BH + o) = bh[u];
            *(uint4*)(smem + SM_BL + o) = bl[u];
        }
    }
    __syncthreads();

    // ---- compute ----
    const int lane = tid & 31, w = tid >> 5;
    const int wr = w >> 1, wc = w & 1;        // warp tile: rows wr*32, cols wc*64

    float acc[2][8][4];
    #pragma unroll
    for (int mt = 0; mt < 2; mt++)
        #pragma unroll
        for (int nt = 0; nt < 8; nt++)
            #pragma unroll
            for (int q = 0; q < 4; q++) acc[mt][nt][q] = 0.f;

    const int arow = wr * 32 + (lane & 15);
    const int akh  = lane >> 4;
    const int brow = wc * 64 + (lane & 7) + ((lane >> 4) << 3);
    const int bkh  = (lane >> 3) & 1;

    #pragma unroll
    for (int s = 0; s < 8; s++) {
        uint32_t afr[2][4];
        #pragma unroll
        for (int mt = 0; mt < 2; mt++)
            ldsm4(afr[mt], sb + SM_A + toff(arow + mt * 16, 2 * s + akh));

        uint32_t bfr[4][4];
        // pass 1: A_hi x B_hi
        #pragma unroll
        for (int np = 0; np < 4; np++)
            ldsm4(bfr[np], sb + SM_BH + toff(brow + np * 16, 2 * s + bkh));
        #pragma unroll
        for (int mt = 0; mt < 2; mt++)
            #pragma unroll
            for (int nt = 0; nt < 8; nt++)
                mma_f16(acc[mt][nt], afr[mt],
                        bfr[nt >> 1][(nt & 1) * 2], bfr[nt >> 1][(nt & 1) * 2 + 1]);
        // pass 2: A_hi x B_lo
        #pragma unroll
        for (int np = 0; np < 4; np++)
            ldsm4(bfr[np], sb + SM_BL + toff(brow + np * 16, 2 * s + bkh));
        #pragma unroll
        for (int mt = 0; mt < 2; mt++)
            #pragma unroll
            for (int nt = 0; nt < 8; nt++)
                mma_f16(acc[mt][nt], afr[mt],
                        bfr[nt >> 1][(nt & 1) * 2], bfr[nt >> 1][(nt & 1) * 2 + 1]);
    }

    // ---- writeout (fp16) ----
    const int rbase = m0 + wr * 32 + (lane >> 2);
    const int cbase = wc * 64 + (lane & 3) * 2;
    #pragma unroll
    for (int mt = 0; mt < 2; mt++) {
        #pragma unroll
        for (int nt = 0; nt < 8; nt++) {
            int n = cbase + nt * 8;
            float bx = 0.f, by = 0.f;
            if (bias) { float2 bv = *(const float2*)&bias[n]; bx = bv.x; by = bv.y; }
            int rr0 = rbase + mt * 16;
            int rr1 = rr0 + 8;
            if (rr0 < M) {
                __half2 o0 = __floats2half2_rn(acc[mt][nt][0] + bx, acc[mt][nt][1] + by);
                *(__half2*)&g_Ph[outOff + (size_t)rr0 * H + n] = o0;
            }
            if (rr1 < M) {
                __half2 o1 = __floats2half2_rn(acc[mt][nt][2] + bx, acc[mt][nt][3] + by);
                *(__half2*)&g_Ph[outOff + (size_t)rr1 * H + n] = o1;
            }
        }
    }
}

// ---------------------------------------------------------------------------
// Kernel 2: per-edge combine on fp16 partials. One warp per edge, x2 ILP.
// ---------------------------------------------------------------------------
__global__ void __launch_bounds__(256)
edge_decode_kernel(const int* __restrict__ edges_gd, const int* __restrict__ edges_gg,
                   const float* __restrict__ w2_gd, const float* __restrict__ b2_gd,
                   const float* __restrict__ w2_gg, const float* __restrict__ b2_gg,
                   float* __restrict__ out, int E, int n_gene, int n_dis)
{
    const int rel = blockIdx.y;
    const size_t ng = (size_t)n_gene * H;
    const size_t nd = (size_t)n_dis * H;

    const int*   edges = rel ? edges_gg : edges_gd;
    const __half* Psrc = rel ? (g_Ph + ng + nd)      : g_Ph;
    const __half* Pdst = rel ? (g_Ph + ng + nd + ng) : (g_Ph + ng);
    const float* w2    = rel ? w2_gg : w2_gd;
    const float  b2    = (rel ? b2_gg : b2_gd)[0];
    float* o = out + (size_t)rel * E;

    const int lane   = threadIdx.x & 31;
    const int warp   = (blockIdx.x * blockDim.x + threadIdx.x) >> 5;
    const int nwarps = (gridDim.x * blockDim.x) >> 5;

    const float4 w = *(const float4*)&w2[lane * 4];

    for (int e = warp; e < E; e += 2 * nwarps) {
        const int e1 = e + nwarps;
        const bool has2 = e1 < E;

        const int s0 = edges[e], d0 = edges[E + e];
        uint2 ua0 = *(const uint2*)&Psrc[(size_t)s0 * H + lane * 4];
        uint2 ub0 = *(const uint2*)&Pdst[(size_t)d0 * H + lane * 4];

        uint2 ua1 = make_uint2(0u, 0u), ub1 = ua1;
        if (has2) {
            const int s1 = edges[e1], d1 = edges[E + e1];
            ua1 = *(const uint2*)&Psrc[(size_t)s1 * H + lane * 4];
            ub1 = *(const uint2*)&Pdst[(size_t)d1 * H + lane * 4];
        }

        float2 fa0 = __half22float2(*(__half2*)&ua0.x);
        float2 fa1 = __half22float2(*(__half2*)&ua0.y);
        float2 fb0 = __half22float2(*(__half2*)&ub0.x);
        float2 fb1 = __half22float2(*(__half2*)&ub0.y);
        float sum0;
        sum0  = fmaxf(fa0.x + fb0.x, 0.f) * w.x;
        sum0 += fmaxf(fa0.y + fb0.y, 0.f) * w.y;
        sum0 += fmaxf(fa1.x + fb1.x, 0.f) * w.z;
        sum0 += fmaxf(fa1.y + fb1.y, 0.f) * w.w;
        #pragma unroll
        for (int off = 16; off; off >>= 1)
            sum0 += __shfl_xor_sync(0xFFFFFFFFu, sum0, off);
        if (lane == 0) o[e] = sum0 + b2;

        if (has2) {
            float2 ga0 = __half22float2(*(__half2*)&ua1.x);
            float2 ga1 = __half22float2(*(__half2*)&ua1.y);
            float2 gb0 = __half22float2(*(__half2*)&ub1.x);
            float2 gb1 = __half22float2(*(__half2*)&ub1.y);
            float sum1;
            sum1  = fmaxf(ga0.x + gb0.x, 0.f) * w.x;
            sum1 += fmaxf(ga0.y + gb0.y, 0.f) * w.y;
            sum1 += fmaxf(ga1.x + gb1.x, 0.f) * w.z;
            sum1 += fmaxf(ga1.y + gb1.y, 0.f) * w.w;
            #pragma unroll
            for (int off = 16; off; off >>= 1)
                sum1 += __shfl_xor_sync(0xFFFFFFFFu, sum1, off);
            if (lane == 0) o[e1] = sum1 + b2;
        }
    }
}

// ---------------------------------------------------------------------------
extern "C" void kernel_launch(void* const* d_in, const int* in_sizes, int n_in,
                              void* d_out, int out_size)
{
    const float* z_gene = (const float*)d_in[0];
    const float* z_dis  = (const float*)d_in[1];
    const int*   e_gd   = (const int*)  d_in[2];
    const int*   e_gg   = (const int*)  d_in[3];
    const float* w1_gd  = (const float*)d_in[4];
    const float* b1_gd  = (const float*)d_in[5];
    const float* w2_gd  = (const float*)d_in[6];
    const float* b2_gd  = (const float*)d_in[7];
    const float* w1_gg  = (const float*)d_in[8];
    const float* b1_gg  = (const float*)d_in[9];
    const float* w2_gg  = (const float*)d_in[10];
    const float* b2_gg  = (const float*)d_in[11];

    const int n_gene = in_sizes[0] / H;
    const int n_dis  = in_sizes[1] / H;
    const int E      = in_sizes[2] / 2;

    static bool attr_done = false;
    if (!attr_done) {
        cudaFuncSetAttribute(gemm_tc_kernel,
                             cudaFuncAttributeMaxDynamicSharedMemorySize, SM_TOTAL);
        attr_done = true;
    }

    prep_w_kernel<<<(4 * H * H + 255) / 256, 256>>>(w1_gd, w1_gg);

    const int tg = (n_gene + 127) >> 7;
    const int td = (n_dis + 127) >> 7;
    gemm_tc_kernel<<<3 * tg + td, 256, SM_TOTAL>>>(z_gene, z_dis, b1_gd, b1_gg,
                                                   n_gene, n_dis);

    dim3 egrid(1184, 2);
    edge_decode_kernel<<<egrid, 256>>>(e_gd, e_gg, w2_gd, b2_gd, w2_gg, b2_gg,
                                       (float*)d_out, E, n_gene, n_dis);
}

// round 5
// speedup vs baseline: 2.0817x; 1.0496x over previous
#include <cuda_runtime.h>
#include <cuda_fp16.h>
#include <cstdint>

#define H 128

// ---------------------------------------------------------------------------
// Global scratch (no allocations allowed)
// ---------------------------------------------------------------------------
// Per-node layer-1 partials in fp16: [gd_gene | gd_dis | gg_src | gg_dst]
__device__ __half g_Ph[42000000];
// fp16 split weights, transposed: [part][hi/lo][n][k]
// part: 0 = w1_gd[:128], 1 = w1_gg[:128], 2 = w1_gg[128:], 3 = w1_gd[128:]
__device__ __half g_Wh[4 * 2 * H * H];

// ---------------------------------------------------------------------------
// helpers
// ---------------------------------------------------------------------------
__device__ __forceinline__ uint32_t smem_u32(const void* p){
    uint32_t a;
    asm("{ .reg .u64 t; cvta.to.shared.u64 t, %1; cvt.u32.u64 %0, t; }" : "=r"(a) : "l"(p));
    return a;
}
__device__ __forceinline__ void ldsm4(uint32_t* r, uint32_t addr){
    asm volatile("ldmatrix.sync.aligned.m8n8.x4.shared.b16 {%0,%1,%2,%3}, [%4];"
        : "=r"(r[0]), "=r"(r[1]), "=r"(r[2]), "=r"(r[3]) : "r"(addr));
}
__device__ __forceinline__ void mma_f16(float* d, const uint32_t* a,
                                        uint32_t b0, uint32_t b1){
    asm volatile("mma.sync.aligned.m16n8k16.row.col.f32.f16.f16.f32 "
        "{%0,%1,%2,%3}, {%4,%5,%6,%7}, {%8,%9}, {%0,%1,%2,%3};"
        : "+f"(d[0]), "+f"(d[1]), "+f"(d[2]), "+f"(d[3])
        : "r"(a[0]), "r"(a[1]), "r"(a[2]), "r"(a[3]), "r"(b0), "r"(b1));
}

// XOR-swizzled byte offset inside a [128 rows x 128 fp16] tile (256B rows).
__device__ __forceinline__ uint32_t toff(int r, int kc){
    return (uint32_t)r * 256u + (uint32_t)((kc ^ (r & 7)) << 4);
}

// smem map: A 32KB | B-hi 32KB | B-lo 32KB
#define SM_A  0
#define SM_BH 32768
#define SM_BL 65536
#define SM_TOTAL 98304

// ---------------------------------------------------------------------------
// Kernel 0: split+transpose the four 128x128 W blocks -> fp16 hi/lo, [n][k]
// ---------------------------------------------------------------------------
__global__ void prep_w_kernel(const float* __restrict__ w1_gd,
                              const float* __restrict__ w1_gg)
{
    int idx = blockIdx.x * blockDim.x + threadIdx.x;  // 4*128*128
    if (idx >= 4 * H * H) return;
    int part = idx >> 14;
    int n = (idx >> 7) & 127;
    int k = idx & 127;
    const float* Wsrc = (part == 0) ? w1_gd
                      : (part == 1) ? w1_gg
                      : (part == 2) ? (w1_gg + H * H)
                                    : (w1_gd + H * H);
    float x = Wsrc[k * H + n];
    __half hi = __float2half_rn(x);
    __half lo = __float2half_rn(x - __half2float(hi));
    g_Wh[((size_t)(part * 2 + 0) * H + n) * H + k] = hi;
    g_Wh[((size_t)(part * 2 + 1) * H + n) * H + k] = lo;
}

// ---------------------------------------------------------------------------
// Kernel 1: tensor-core GEMM. A staged ONCE per tile; gene tiles loop over
// three weight matrices (parts 0,1,2), disease tiles do part 3 only.
// C = A_hi @ (B_hi + B_lo)^T, fp32 accum, fp16 out.
// ---------------------------------------------------------------------------
__global__ void __launch_bounds__(256, 2)
gemm_tc_kernel(const float* __restrict__ zg, const float* __restrict__ zd,
               const float* __restrict__ b1_gd, const float* __restrict__ b1_gg,
               int n_gene, int n_dis)
{
    extern __shared__ char smem[];
    const uint32_t sb = smem_u32(smem);
    const int tid = threadIdx.x;

    const int tg = (n_gene + 127) >> 7;
    const size_t ng = (size_t)n_gene * H, nd = (size_t)n_dis * H;

    const int b = blockIdx.x;
    const bool isGene = (b < tg);
    const float* A = isGene ? zg : zd;
    const int M = isGene ? n_gene : n_dis;
    const int m0 = (isGene ? b : (b - tg)) << 7;
    const int nparts = isGene ? 3 : 1;

    // ---- stage A (fp32 -> fp16 hi) once ----
    #pragma unroll
    for (int i = 0; i < 8; i++) {
        int u = tid + 256 * i;          // (row, 16B chunk)
        int r = u >> 4, c8 = u & 15;
        float4 v0 = make_float4(0.f,0.f,0.f,0.f), v1 = v0;
        if (m0 + r < M) {
            const float* ap = &A[(size_t)(m0 + r) * H + c8 * 8];
            v0 = *(const float4*)ap;
            v1 = *(const float4*)(ap + 4);
        }
        __half2 h0 = __floats2half2_rn(v0.x, v0.y);
        __half2 h1 = __floats2half2_rn(v0.z, v0.w);
        __half2 h2 = __floats2half2_rn(v1.x, v1.y);
        __half2 h3 = __floats2half2_rn(v1.z, v1.w);
        uint4 pk = make_uint4(*(uint32_t*)&h0, *(uint32_t*)&h1,
                              *(uint32_t*)&h2, *(uint32_t*)&h3);
        *(uint4*)(smem + SM_A + toff(r, c8)) = pk;
    }

    const int lane = tid & 31, w = tid >> 5;
    const int wr = w >> 1, wc = w & 1;
    const int arow = wr * 32 + (lane & 15);
    const int akh  = lane >> 4;
    const int brow = wc * 64 + (lane & 7) + ((lane >> 4) << 3);
    const int bkh  = (lane >> 3) & 1;
    const int rbase = m0 + wr * 32 + (lane >> 2);
    const int cbase = wc * 64 + (lane & 3) * 2;

    for (int p = 0; p < nparts; p++) {
        const int part = isGene ? p : 3;
        const float* bias = (part == 2) ? b1_gg : (part == 3) ? b1_gd : nullptr;
        const size_t outOff = (part == 0) ? 0
                            : (part == 1) ? (ng + nd)
                            : (part == 2) ? (ng + nd + ng)
                                          : ng;

        // ---- stage B hi/lo for this part ----
        {
            const uint4* bh = (const uint4*)(g_Wh + (size_t)(part * 2 + 0) * H * H);
            const uint4* bl = (const uint4*)(g_Wh + (size_t)(part * 2 + 1) * H * H);
            #pragma unroll
            for (int i = 0; i < 8; i++) {
                int u = tid + 256 * i;
                int r = u >> 4, kc = u & 15;
                uint32_t o = toff(r, kc);
                *(uint4*)(smem + SM_BH + o) = bh[u];
                *(uint4*)(smem + SM_BL + o) = bl[u];
            }
        }
        __syncthreads();

        // ---- compute ----
        float acc[2][8][4];
        #pragma unroll
        for (int mt = 0; mt < 2; mt++)
            #pragma unroll
            for (int nt = 0; nt < 8; nt++)
                #pragma unroll
                for (int q = 0; q < 4; q++) acc[mt][nt][q] = 0.f;

        #pragma unroll
        for (int s = 0; s < 8; s++) {
            uint32_t afr[2][4];
            #pragma unroll
            for (int mt = 0; mt < 2; mt++)
                ldsm4(afr[mt], sb + SM_A + toff(arow + mt * 16, 2 * s + akh));

            uint32_t bfr[4][4];
            #pragma unroll
            for (int np = 0; np < 4; np++)
                ldsm4(bfr[np], sb + SM_BH + toff(brow + np * 16, 2 * s + bkh));
            #pragma unroll
            for (int mt = 0; mt < 2; mt++)
                #pragma unroll
                for (int nt = 0; nt < 8; nt++)
                    mma_f16(acc[mt][nt], afr[mt],
                            bfr[nt >> 1][(nt & 1) * 2], bfr[nt >> 1][(nt & 1) * 2 + 1]);

            #pragma unroll
            for (int np = 0; np < 4; np++)
                ldsm4(bfr[np], sb + SM_BL + toff(brow + np * 16, 2 * s + bkh));
            #pragma unroll
            for (int mt = 0; mt < 2; mt++)
                #pragma unroll
                for (int nt = 0; nt < 8; nt++)
                    mma_f16(acc[mt][nt], afr[mt],
                            bfr[nt >> 1][(nt & 1) * 2], bfr[nt >> 1][(nt & 1) * 2 + 1]);
        }

        // ---- writeout (fp16) ----
        #pragma unroll
        for (int mt = 0; mt < 2; mt++) {
            #pragma unroll
            for (int nt = 0; nt < 8; nt++) {
                int n = cbase + nt * 8;
                float bx = 0.f, by = 0.f;
                if (bias) { float2 bv = *(const float2*)&bias[n]; bx = bv.x; by = bv.y; }
                int rr0 = rbase + mt * 16;
                int rr1 = rr0 + 8;
                if (rr0 < M) {
                    __half2 o0 = __floats2half2_rn(acc[mt][nt][0] + bx, acc[mt][nt][1] + by);
                    *(__half2*)&g_Ph[outOff + (size_t)rr0 * H + n] = o0;
                }
                if (rr1 < M) {
                    __half2 o1 = __floats2half2_rn(acc[mt][nt][2] + bx, acc[mt][nt][3] + by);
                    *(__half2*)&g_Ph[outOff + (size_t)rr1 * H + n] = o1;
                }
            }
        }
        __syncthreads();  // all warps done with B before next part overwrites it
    }
}

// ---------------------------------------------------------------------------
// Kernel 2: per-edge combine on fp16 partials. One warp per edge, x2 ILP.
// ---------------------------------------------------------------------------
__global__ void __launch_bounds__(256)
edge_decode_kernel(const int* __restrict__ edges_gd, const int* __restrict__ edges_gg,
                   const float* __restrict__ w2_gd, const float* __restrict__ b2_gd,
                   const float* __restrict__ w2_gg, const float* __restrict__ b2_gg,
                   float* __restrict__ out, int E, int n_gene, int n_dis)
{
    const int rel = blockIdx.y;
    const size_t ng = (size_t)n_gene * H;
    const size_t nd = (size_t)n_dis * H;

    const int*   edges = rel ? edges_gg : edges_gd;
    const __half* Psrc = rel ? (g_Ph + ng + nd)      : g_Ph;
    const __half* Pdst = rel ? (g_Ph + ng + nd + ng) : (g_Ph + ng);
    const float* w2    = rel ? w2_gg : w2_gd;
    const float  b2    = (rel ? b2_gg : b2_gd)[0];
    float* o = out + (size_t)rel * E;

    const int lane   = threadIdx.x & 31;
    const int warp   = (blockIdx.x * blockDim.x + threadIdx.x) >> 5;
    const int nwarps = (gridDim.x * blockDim.x) >> 5;

    const float4 w = *(const float4*)&w2[lane * 4];

    for (int e = warp; e < E; e += 2 * nwarps) {
        const int e1 = e + nwarps;
        const bool has2 = e1 < E;

        const int s0 = edges[e], d0 = edges[E + e];
        uint2 ua0 = *(const uint2*)&Psrc[(size_t)s0 * H + lane * 4];
        uint2 ub0 = *(const uint2*)&Pdst[(size_t)d0 * H + lane * 4];

        uint2 ua1 = make_uint2(0u, 0u), ub1 = ua1;
        if (has2) {
            const int s1 = edges[e1], d1 = edges[E + e1];
            ua1 = *(const uint2*)&Psrc[(size_t)s1 * H + lane * 4];
            ub1 = *(const uint2*)&Pdst[(size_t)d1 * H + lane * 4];
        }

        float2 fa0 = __half22float2(*(__half2*)&ua0.x);
        float2 fa1 = __half22float2(*(__half2*)&ua0.y);
        float2 fb0 = __half22float2(*(__half2*)&ub0.x);
        float2 fb1 = __half22float2(*(__half2*)&ub0.y);
        float sum0;
        sum0  = fmaxf(fa0.x + fb0.x, 0.f) * w.x;
        sum0 += fmaxf(fa0.y + fb0.y, 0.f) * w.y;
        sum0 += fmaxf(fa1.x + fb1.x, 0.f) * w.z;
        sum0 += fmaxf(fa1.y + fb1.y, 0.f) * w.w;
        #pragma unroll
        for (int off = 16; off; off >>= 1)
            sum0 += __shfl_xor_sync(0xFFFFFFFFu, sum0, off);
        if (lane == 0) o[e] = sum0 + b2;

        if (has2) {
            float2 ga0 = __half22float2(*(__half2*)&ua1.x);
            float2 ga1 = __half22float2(*(__half2*)&ua1.y);
            float2 gb0 = __half22float2(*(__half2*)&ub1.x);
            float2 gb1 = __half22float2(*(__half2*)&ub1.y);
            float sum1;
            sum1  = fmaxf(ga0.x + gb0.x, 0.f) * w.x;
            sum1 += fmaxf(ga0.y + gb0.y, 0.f) * w.y;
            sum1 += fmaxf(ga1.x + gb1.x, 0.f) * w.z;
            sum1 += fmaxf(ga1.y + gb1.y, 0.f) * w.w;
            #pragma unroll
            for (int off = 16; off; off >>= 1)
                sum1 += __shfl_xor_sync(0xFFFFFFFFu, sum1, off);
            if (lane == 0) o[e1] = sum1 + b2;
        }
    }
}

// ---------------------------------------------------------------------------
extern "C" void kernel_launch(void* const* d_in, const int* in_sizes, int n_in,
                              void* d_out, int out_size)
{
    const float* z_gene = (const float*)d_in[0];
    const float* z_dis  = (const float*)d_in[1];
    const int*   e_gd   = (const int*)  d_in[2];
    const int*   e_gg   = (const int*)  d_in[3];
    const float* w1_gd  = (const float*)d_in[4];
    const float* b1_gd  = (const float*)d_in[5];
    const float* w2_gd  = (const float*)d_in[6];
    const float* b2_gd  = (const float*)d_in[7];
    const float* w1_gg  = (const float*)d_in[8];
    const float* b1_gg  = (const float*)d_in[9];
    const float* w2_gg  = (const float*)d_in[10];
    const float* b2_gg  = (const float*)d_in[11];

    const int n_gene = in_sizes[0] / H;
    const int n_dis  = in_sizes[1] / H;
    const int E      = in_sizes[2] / 2;

    static bool attr_done = false;
    if (!attr_done) {
        cudaFuncSetAttribute(gemm_tc_kernel,
                             cudaFuncAttributeMaxDynamicSharedMemorySize, SM_TOTAL);
        attr_done = true;
    }

    prep_w_kernel<<<(4 * H * H + 255) / 256, 256>>>(w1_gd, w1_gg);

    const int tg = (n_gene + 127) >> 7;
    const int td = (n_dis + 127) >> 7;
    gemm_tc_kernel<<<tg + td, 256, SM_TOTAL>>>(z_gene, z_dis, b1_gd, b1_gg,
                                               n_gene, n_dis);

    dim3 egrid(1184, 2);
    edge_decode_kernel<<<egrid, 256>>>(e_gd, e_gg, w2_gd, b2_gd, w2_gg, b2_gg,
                                       (float*)d_out, E, n_gene, n_dis);
}